// round 10
// baseline (speedup 1.0000x reference)
#include <cuda_runtime.h>
#include <math.h>
#include <cstdint>

#define BATCH 64
#define SEQ   512
#define EDIM  256
#define HDIM2 256
#define G4H   1024
#define NTAGS 9
#define NTOK  (BATCH*SEQ)

typedef unsigned long long u64;

__device__ float g_xg[2u*NTOK*G4H];
__device__ float g_h [2u*NTOK*HDIM2];
__device__ float g_feats[NTOK*NTAGS];
__device__ float g_llh[BATCH];
__device__ int   g_cnt[16];   // per-(dir,bg8) step counters

__device__ __forceinline__ void fma2(u64& acc, u64 a, u64 b) {
    asm("fma.rn.f32x2 %0, %1, %2, %0;" : "+l"(acc) : "l"(a), "l"(b));
}
__device__ __forceinline__ u64 pack2(float x, float y) {
    u64 r; asm("mov.b64 %0, {%1, %2};" : "=l"(r) : "f"(x), "f"(y)); return r;
}
__device__ __forceinline__ float foldlohi(u64 v) {
    float lo, hi; asm("mov.b64 {%0, %1}, %2;" : "=f"(lo), "=f"(hi) : "l"(v)); return lo + hi;
}
__device__ __forceinline__ float2 unpk(u64 v) {
    float2 r; asm("mov.b64 {%0, %1}, %2;" : "=f"(r.x), "=f"(r.y) : "l"(v)); return r;
}
__device__ __forceinline__ float sigf(float x) { return __fdividef(1.f, 1.f + __expf(-x)); }
__device__ __forceinline__ float tanhfast(float x) {
    return 2.f * __fdividef(1.f, 1.f + __expf(-2.f * x)) - 1.f;
}

// ============================================================================
// Kernel 1: fused embedding-gather + input projection SGEMM (f32x2)
//   M=32768, N=2048 (dir-major), K=256. BM=128, BN=128, BK=16, 256 thr, 8x8.
// ============================================================================
__global__ __launch_bounds__(256) void gemm_xg_kernel(
    const int* __restrict__ sent,
    const float* __restrict__ emb,
    const float* __restrict__ wihf, const float* __restrict__ wihb,
    const float* __restrict__ bihf, const float* __restrict__ bhhf,
    const float* __restrict__ bihb, const float* __restrict__ bhhb)
{
    __shared__ float As[16 * 132];
    __shared__ float Bs[16 * 128];

    const int tid = threadIdx.x;
    if (blockIdx.x == 0 && blockIdx.y == 0 && tid < 16) g_cnt[tid] = 0;  // reset lstm counters

    const int ntile = blockIdx.x;
    const int mtile = blockIdx.y;
    const int dir   = ntile >> 3;
    const float* __restrict__ W = dir ? wihb : wihf;

    const int rowA = tid >> 2;
    const int f4k  = tid & 3;
    const int idx0 = sent[mtile * 128 + rowA];
    const int idx1 = sent[mtile * 128 + rowA + 64];
    const int nlb0 = (ntile * 128 + rowA) & 1023;
    const int nlb1 = (ntile * 128 + rowA + 64) & 1023;

    float4 av0 = *reinterpret_cast<const float4*>(emb + (size_t)idx0 * EDIM + f4k * 4);
    float4 av1 = *reinterpret_cast<const float4*>(emb + (size_t)idx1 * EDIM + f4k * 4);
    float4 bv0 = *reinterpret_cast<const float4*>(W + (size_t)nlb0 * EDIM + f4k * 4);
    float4 bv1 = *reinterpret_cast<const float4*>(W + (size_t)nlb1 * EDIM + f4k * 4);

    u64 acc[4][8];
#pragma unroll
    for (int i = 0; i < 4; i++)
#pragma unroll
        for (int j = 0; j < 8; j++) acc[i][j] = 0ull;

    const int ty = tid >> 4, tx = tid & 15;

    for (int kb = 0; kb < EDIM; kb += 16) {
        As[(f4k * 4 + 0) * 132 + rowA] = av0.x;
        As[(f4k * 4 + 1) * 132 + rowA] = av0.y;
        As[(f4k * 4 + 2) * 132 + rowA] = av0.z;
        As[(f4k * 4 + 3) * 132 + rowA] = av0.w;
        As[(f4k * 4 + 0) * 132 + rowA + 64] = av1.x;
        As[(f4k * 4 + 1) * 132 + rowA + 64] = av1.y;
        As[(f4k * 4 + 2) * 132 + rowA + 64] = av1.z;
        As[(f4k * 4 + 3) * 132 + rowA + 64] = av1.w;
        Bs[(f4k * 4 + 0) * 128 + rowA] = bv0.x;
        Bs[(f4k * 4 + 1) * 128 + rowA] = bv0.y;
        Bs[(f4k * 4 + 2) * 128 + rowA] = bv0.z;
        Bs[(f4k * 4 + 3) * 128 + rowA] = bv0.w;
        Bs[(f4k * 4 + 0) * 128 + rowA + 64] = bv1.x;
        Bs[(f4k * 4 + 1) * 128 + rowA + 64] = bv1.y;
        Bs[(f4k * 4 + 2) * 128 + rowA + 64] = bv1.z;
        Bs[(f4k * 4 + 3) * 128 + rowA + 64] = bv1.w;
        __syncthreads();

        if (kb + 16 < EDIM) {
            av0 = *reinterpret_cast<const float4*>(emb + (size_t)idx0 * EDIM + kb + 16 + f4k * 4);
            av1 = *reinterpret_cast<const float4*>(emb + (size_t)idx1 * EDIM + kb + 16 + f4k * 4);
            bv0 = *reinterpret_cast<const float4*>(W + (size_t)nlb0 * EDIM + kb + 16 + f4k * 4);
            bv1 = *reinterpret_cast<const float4*>(W + (size_t)nlb1 * EDIM + kb + 16 + f4k * 4);
        }

#pragma unroll
        for (int k = 0; k < 16; k++) {
            const float* ap = As + k * 132 + ty * 8;
            ulonglong2 A01 = *reinterpret_cast<const ulonglong2*>(ap);
            ulonglong2 A23 = *reinterpret_cast<const ulonglong2*>(ap + 4);
            const float* bp = Bs + k * 128 + tx * 8;
            float4 b0 = *reinterpret_cast<const float4*>(bp);
            float4 b1 = *reinterpret_cast<const float4*>(bp + 4);
            u64 am[4] = {A01.x, A01.y, A23.x, A23.y};
            u64 bn[8];
            bn[0] = pack2(b0.x, b0.x); bn[1] = pack2(b0.y, b0.y);
            bn[2] = pack2(b0.z, b0.z); bn[3] = pack2(b0.w, b0.w);
            bn[4] = pack2(b1.x, b1.x); bn[5] = pack2(b1.y, b1.y);
            bn[6] = pack2(b1.z, b1.z); bn[7] = pack2(b1.w, b1.w);
#pragma unroll
            for (int i = 0; i < 4; i++)
#pragma unroll
                for (int j = 0; j < 8; j++) fma2(acc[i][j], am[i], bn[j]);
        }
        __syncthreads();
    }

    const int n0  = ntile * 128 + tx * 8;
    const int nl0 = n0 & 1023;
    const float* __restrict__ bih = dir ? bihb : bihf;
    const float* __restrict__ bhh = dir ? bhhb : bhhf;
    float bias[8];
#pragma unroll
    for (int j = 0; j < 8; j++) bias[j] = bih[nl0 + j] + bhh[nl0 + j];

#pragma unroll
    for (int i2 = 0; i2 < 4; i2++) {
        float2 v[8];
#pragma unroll
        for (int j = 0; j < 8; j++) v[j] = unpk(acc[i2][j]);
        const int m0 = mtile * 128 + ty * 8 + 2 * i2;
        float4 oa0, oa1, ob0, ob1;
        oa0.x = v[0].x + bias[0]; oa0.y = v[1].x + bias[1]; oa0.z = v[2].x + bias[2]; oa0.w = v[3].x + bias[3];
        oa1.x = v[4].x + bias[4]; oa1.y = v[5].x + bias[5]; oa1.z = v[6].x + bias[6]; oa1.w = v[7].x + bias[7];
        ob0.x = v[0].y + bias[0]; ob0.y = v[1].y + bias[1]; ob0.z = v[2].y + bias[2]; ob0.w = v[3].y + bias[3];
        ob1.x = v[4].y + bias[4]; ob1.y = v[5].y + bias[5]; ob1.z = v[6].y + bias[6]; ob1.w = v[7].y + bias[7];
        float* p0 = g_xg + ((size_t)dir * NTOK + m0) * G4H + nl0;
        float* p1 = g_xg + ((size_t)dir * NTOK + m0 + 1) * G4H + nl0;
        *reinterpret_cast<float4*>(p0)     = oa0;
        *reinterpret_cast<float4*>(p0 + 4) = oa1;
        *reinterpret_cast<float4*>(p1)     = ob0;
        *reinterpret_cast<float4*>(p1 + 4) = ob1;
    }
}

// ============================================================================
// Kernel 2: persistent BiLSTM, dual-group software pipeline.
//   64 CTAs = dir(2) x p(4) x ug(8). CTA owns 32 units and TWO independent
//   8-batch groups (bg = 2p, 2p+1). Per step: full phase for group A, then
//   group B. Peers release A(t) before starting B(t), and we arrive at
//   waitA(t+1) only after our own ~3K-cycle B(t) phase -> flag already set:
//   spin discovery + straggler jitter leave the critical path.
//   Weights (dir,ug slice) shared by both groups: 4 gate rows x 32 k = 128 regs.
//   Handshake = R9-proven counter (fence + RED-add, tid0 spin).
// ============================================================================
#define HLD    260
#define PRE_LD 65

__global__ __launch_bounds__(256, 1) void lstm_kernel(
    const float* __restrict__ whhf, const float* __restrict__ whhb)
{
    __shared__ float hs[8 * HLD];        // staged h_prev [batch][256] (reused A/B)
    __shared__ float pre[128 * PRE_LD];  // [row][kc*8 + b]            (reused A/B)

    const int tid = threadIdx.x;
    const int blk = blockIdx.x;
    const int dir = blk >> 5;
    const int p   = (blk >> 3) & 3;
    const int ug  = blk & 7;
    const float* __restrict__ whh = dir ? whhb : whhf;

    const int kc = tid & 7;           // k slice
    const int r4 = tid >> 3;          // local unit 0..31 -> rows G*256 + ug*32 + r4

    // register weights: 4 gate rows x 32 k (16 pairs) each — shared by both groups
    u64 w[4][16];
#pragma unroll
    for (int G = 0; G < 4; G++) {
        const float* wr = whh + (size_t)(G * 256 + ug * 32 + r4) * HDIM2;
#pragma unroll
        for (int q = 0; q < 8; q++) {
            ulonglong2 v = *reinterpret_cast<const ulonglong2*>(wr + q * 32 + kc * 4);
            w[G][2 * q] = v.x; w[G][2 * q + 1] = v.y;
        }
    }

    const int gb = tid >> 5;          // gate phase: batch 0..7
    const int gu = tid & 31;          // unit-in-slice 0..31
    const int unit = ug * 32 + gu;
    float cs[2] = {0.f, 0.f};         // c_state per group

    for (int t = 0; t < SEQ; t++) {
        const int pos = dir ? (SEQ - 1 - t) : t;
        const int ppos = dir ? (pos + 1) : (pos - 1);

#pragma unroll
        for (int sub = 0; sub < 2; sub++) {
            const int bg = 2 * p + sub;
            const int b_glob = bg * 8 + gb;
            const int cnt_idx = dir * 8 + bg;

            // prefetch x-preacts for this group (overlaps any residual wait)
            const float* xp = g_xg + ((size_t)dir * NTOK + (size_t)b_glob * SEQ + pos) * G4H + unit;
            float x0 = __ldcs(xp);
            float x1 = __ldcs(xp + 256);
            float x2 = __ldcs(xp + 512);
            float x3 = __ldcs(xp + 768);

            if (t > 0) {
                if (tid == 0) {
                    volatile int* c = &g_cnt[cnt_idx];
                    const int target = 8 * t;
                    while (*c < target) { }
                }
                __syncthreads();
                // stage h_prev for this group's 8 batches
#pragma unroll
                for (int q = 0; q < 2; q++) {
                    const int id = tid + q * 256;
                    const int b = id >> 6, kf4 = id & 63;
                    float4 v = __ldcg(reinterpret_cast<const float4*>(
                        g_h + ((size_t)(dir * BATCH + bg * 8 + b) * SEQ + ppos) * HDIM2 + kf4 * 4));
                    *reinterpret_cast<float4*>(hs + b * HLD + kf4 * 4) = v;
                }
                __syncthreads();

                // matvec: 4 gate rows x 8 batches x 32 k, in 2 passes of 4 batches
#pragma unroll
                for (int pp = 0; pp < 2; pp++) {
                    u64 acc[4][4];
#pragma unroll
                    for (int G = 0; G < 4; G++)
#pragma unroll
                        for (int b = 0; b < 4; b++) acc[G][b] = 0ull;
#pragma unroll
                    for (int q = 0; q < 8; q++) {
#pragma unroll
                        for (int b = 0; b < 4; b++) {
                            const ulonglong2 hv = *reinterpret_cast<const ulonglong2*>(
                                hs + (pp * 4 + b) * HLD + q * 32 + kc * 4);
#pragma unroll
                            for (int G = 0; G < 4; G++) {
                                fma2(acc[G][b], w[G][2 * q],     hv.x);
                                fma2(acc[G][b], w[G][2 * q + 1], hv.y);
                            }
                        }
                    }
#pragma unroll
                    for (int G = 0; G < 4; G++)
#pragma unroll
                        for (int b = 0; b < 4; b++)
                            pre[(G * 32 + r4) * PRE_LD + kc * 8 + pp * 4 + b] = foldlohi(acc[G][b]);
                }
                __syncthreads();
            }

            // gate phase: thread owns (batch gb, unit gu)
            {
                float pi = x0, pf = x1, pg = x2, po = x3;
                if (t > 0) {
#pragma unroll
                    for (int k8 = 0; k8 < 8; k8++) {
                        pi += pre[(0 * 32 + gu) * PRE_LD + k8 * 8 + gb];
                        pf += pre[(1 * 32 + gu) * PRE_LD + k8 * 8 + gb];
                        pg += pre[(2 * 32 + gu) * PRE_LD + k8 * 8 + gb];
                        po += pre[(3 * 32 + gu) * PRE_LD + k8 * 8 + gb];
                    }
                }
                cs[sub] = sigf(pf) * cs[sub] + sigf(pi) * tanhfast(pg);
                const float hv = sigf(po) * tanhfast(cs[sub]);
                __stcg(&g_h[((size_t)(dir * BATCH + b_glob) * SEQ + pos) * HDIM2 + unit], hv);
            }

            __syncthreads();
            if (tid == 0) {
                __threadfence();
                atomicAdd(&g_cnt[cnt_idx], 1);   // result unused -> RED
            }
        }
    }
}

// ============================================================================
// Kernel 3: output projection
// ============================================================================
__global__ __launch_bounds__(256) void feats_kernel(
    const float* __restrict__ wout, const float* __restrict__ bout)
{
    __shared__ float wsm[NTAGS * 512];
    const int tid = threadIdx.x;
    for (int i = tid; i < NTAGS * 512; i += 256) wsm[i] = wout[i];
    __syncthreads();

    const int lane = tid & 31;
    const int warp = tid >> 5;

#pragma unroll
    for (int pass = 0; pass < 4; pass++) {
        const int m = blockIdx.x * 32 + pass * 8 + warp;
        const float* h0 = g_h + (size_t)m * HDIM2;
        const float* h1 = g_h + (size_t)NTOK * HDIM2 + (size_t)m * HDIM2;
        float acc[NTAGS];
#pragma unroll
        for (int tg = 0; tg < NTAGS; tg++) acc[tg] = 0.f;

#pragma unroll
        for (int kk = 0; kk < 16; kk++) {
            const int k = kk * 32 + lane;
            const float hv = (k < 256) ? h0[k] : h1[k - 256];
#pragma unroll
            for (int tg = 0; tg < NTAGS; tg++) acc[tg] += hv * wsm[tg * 512 + k];
        }
#pragma unroll
        for (int tg = 0; tg < NTAGS; tg++)
            for (int off = 16; off; off >>= 1)
                acc[tg] += __shfl_down_sync(0xffffffffu, acc[tg], off);
        if (lane == 0) {
#pragma unroll
            for (int tg = 0; tg < NTAGS; tg++)
                g_feats[(size_t)m * NTAGS + tg] = acc[tg] + bout[tg];
        }
    }
}

// ============================================================================
// Kernel 4: CRF per-sequence llh (mask all-ones)
// ============================================================================
__global__ __launch_bounds__(32) void crf_kernel(
    const int* __restrict__ tags,
    const float* __restrict__ startt, const float* __restrict__ endt,
    const float* __restrict__ trans)
{
    const int b = blockIdx.x;
    const int lane = threadIdx.x;
    const float* __restrict__ em = g_feats + (size_t)b * SEQ * NTAGS;
    const int* __restrict__ tg = tags + (size_t)b * SEQ;

    float sc = 0.f;
    for (int s = lane; s < SEQ; s += 32) {
        const int tc = tg[s];
        sc += em[s * NTAGS + tc];
        if (s > 0) sc += trans[tg[s - 1] * NTAGS + tc];
    }
    for (int off = 16; off; off >>= 1) sc += __shfl_down_sync(0xffffffffu, sc, off);

    const int j = lane < NTAGS ? lane : NTAGS - 1;
    float tcol[NTAGS];
#pragma unroll
    for (int i = 0; i < NTAGS; i++) tcol[i] = trans[i * NTAGS + j];

    float alpha = startt[j] + em[j];
    for (int s = 1; s < SEQ; s++) {
        float v[NTAGS];
        float mx = -1e30f;
#pragma unroll
        for (int i = 0; i < NTAGS; i++) {
            const float ai = __shfl_sync(0xffffffffu, alpha, i);
            v[i] = ai + tcol[i];
            mx = fmaxf(mx, v[i]);
        }
        float sum = 0.f;
#pragma unroll
        for (int i = 0; i < NTAGS; i++) sum += __expf(v[i] - mx);
        alpha = mx + __logf(sum) + em[s * NTAGS + j];
    }

    float z = (lane < NTAGS) ? (alpha + endt[j]) : -1e30f;
    float mz = z;
    for (int off = 16; off; off >>= 1) mz = fmaxf(mz, __shfl_down_sync(0xffffffffu, mz, off));
    mz = __shfl_sync(0xffffffffu, mz, 0);
    float ez = __expf(z - mz);
    for (int off = 16; off; off >>= 1) ez += __shfl_down_sync(0xffffffffu, ez, off);

    if (lane == 0) {
        const float logZ = mz + __logf(ez);
        const float score = sc + startt[tg[0]] + endt[tg[SEQ - 1]];
        g_llh[b] = score - logZ;
    }
}

__global__ void final_kernel(float* out) {
    __shared__ float red[64];
    const int t = threadIdx.x;
    red[t] = g_llh[t];
    __syncthreads();
    for (int off = 32; off; off >>= 1) {
        if (t < off) red[t] += red[t + off];
        __syncthreads();
    }
    if (t == 0) out[0] = -red[0] / (float)BATCH;
}

// ============================================================================
extern "C" void kernel_launch(void* const* d_in, const int* in_sizes, int n_in,
                              void* d_out, int out_size)
{
    const int*   sent  = (const int*)  d_in[0];
    const int*   tags  = (const int*)  d_in[1];
    const float* emb   = (const float*)d_in[3];
    const float* wihf  = (const float*)d_in[4];
    const float* whhf  = (const float*)d_in[5];
    const float* bihf  = (const float*)d_in[6];
    const float* bhhf  = (const float*)d_in[7];
    const float* wihb  = (const float*)d_in[8];
    const float* whhb  = (const float*)d_in[9];
    const float* bihb  = (const float*)d_in[10];
    const float* bhhb  = (const float*)d_in[11];
    const float* wout  = (const float*)d_in[12];
    const float* bout  = (const float*)d_in[13];
    const float* startt= (const float*)d_in[14];
    const float* endt  = (const float*)d_in[15];
    const float* trans = (const float*)d_in[16];

    gemm_xg_kernel<<<dim3(16, 256), 256>>>(sent, emb, wihf, wihb, bihf, bhhf, bihb, bhhb);
    lstm_kernel<<<64, 256>>>(whhf, whhb);
    feats_kernel<<<1024, 256>>>(wout, bout);
    crf_kernel<<<64, 32>>>(tags, startt, endt, trans);
    final_kernel<<<1, 64>>>((float*)d_out);
}

// round 11
// speedup vs baseline: 1.6005x; 1.6005x over previous
#include <cuda_runtime.h>
#include <math.h>
#include <cstdint>

#define BATCH 64
#define SEQ   512
#define EDIM  256
#define HDIM2 256
#define G4H   1024
#define NTAGS 9
#define NTOK  (BATCH*SEQ)

typedef unsigned long long u64;

__device__ float g_xg[2u*NTOK*G4H];
__device__ float g_h [2u*NTOK*HDIM2];
__device__ float g_feats[NTOK*NTAGS];
__device__ float g_llh[BATCH];
__device__ int   g_cnt[16];   // per-(dir,bg8) step counters

__device__ __forceinline__ void fma2(u64& acc, u64 a, u64 b) {
    asm("fma.rn.f32x2 %0, %1, %2, %0;" : "+l"(acc) : "l"(a), "l"(b));
}
__device__ __forceinline__ u64 pack2(float x, float y) {
    u64 r; asm("mov.b64 %0, {%1, %2};" : "=l"(r) : "f"(x), "f"(y)); return r;
}
__device__ __forceinline__ float foldlohi(u64 v) {
    float lo, hi; asm("mov.b64 {%0, %1}, %2;" : "=f"(lo), "=f"(hi) : "l"(v)); return lo + hi;
}
__device__ __forceinline__ float2 unpk(u64 v) {
    float2 r; asm("mov.b64 {%0, %1}, %2;" : "=f"(r.x), "=f"(r.y) : "l"(v)); return r;
}
__device__ __forceinline__ float sigf(float x) { return __fdividef(1.f, 1.f + __expf(-x)); }
__device__ __forceinline__ float tanhfast(float x) {
    return 2.f * __fdividef(1.f, 1.f + __expf(-2.f * x)) - 1.f;
}
__device__ __forceinline__ int ld_acq_gpu(const int* p) {
    int v; asm volatile("ld.acquire.gpu.global.s32 %0, [%1];" : "=r"(v) : "l"(p) : "memory");
    return v;
}
__device__ __forceinline__ void red_add_release_gpu(int* p) {
    asm volatile("red.release.gpu.global.add.s32 [%0], 1;" :: "l"(p) : "memory");
}

// ============================================================================
// Kernel 1: fused embedding-gather + input projection SGEMM (f32x2)
//   M=32768, N=2048 (dir-major), K=256. BM=128, BN=128, BK=16, 256 thr, 8x8.
// ============================================================================
__global__ __launch_bounds__(256) void gemm_xg_kernel(
    const int* __restrict__ sent,
    const float* __restrict__ emb,
    const float* __restrict__ wihf, const float* __restrict__ wihb,
    const float* __restrict__ bihf, const float* __restrict__ bhhf,
    const float* __restrict__ bihb, const float* __restrict__ bhhb)
{
    __shared__ float As[16 * 132];
    __shared__ float Bs[16 * 128];

    const int tid = threadIdx.x;
    if (blockIdx.x == 0 && blockIdx.y == 0 && tid < 16) g_cnt[tid] = 0;  // reset lstm counters

    const int ntile = blockIdx.x;
    const int mtile = blockIdx.y;
    const int dir   = ntile >> 3;
    const float* __restrict__ W = dir ? wihb : wihf;

    const int rowA = tid >> 2;
    const int f4k  = tid & 3;
    const int idx0 = sent[mtile * 128 + rowA];
    const int idx1 = sent[mtile * 128 + rowA + 64];
    const int nlb0 = (ntile * 128 + rowA) & 1023;
    const int nlb1 = (ntile * 128 + rowA + 64) & 1023;

    float4 av0 = *reinterpret_cast<const float4*>(emb + (size_t)idx0 * EDIM + f4k * 4);
    float4 av1 = *reinterpret_cast<const float4*>(emb + (size_t)idx1 * EDIM + f4k * 4);
    float4 bv0 = *reinterpret_cast<const float4*>(W + (size_t)nlb0 * EDIM + f4k * 4);
    float4 bv1 = *reinterpret_cast<const float4*>(W + (size_t)nlb1 * EDIM + f4k * 4);

    u64 acc[4][8];
#pragma unroll
    for (int i = 0; i < 4; i++)
#pragma unroll
        for (int j = 0; j < 8; j++) acc[i][j] = 0ull;

    const int ty = tid >> 4, tx = tid & 15;

    for (int kb = 0; kb < EDIM; kb += 16) {
        As[(f4k * 4 + 0) * 132 + rowA] = av0.x;
        As[(f4k * 4 + 1) * 132 + rowA] = av0.y;
        As[(f4k * 4 + 2) * 132 + rowA] = av0.z;
        As[(f4k * 4 + 3) * 132 + rowA] = av0.w;
        As[(f4k * 4 + 0) * 132 + rowA + 64] = av1.x;
        As[(f4k * 4 + 1) * 132 + rowA + 64] = av1.y;
        As[(f4k * 4 + 2) * 132 + rowA + 64] = av1.z;
        As[(f4k * 4 + 3) * 132 + rowA + 64] = av1.w;
        Bs[(f4k * 4 + 0) * 128 + rowA] = bv0.x;
        Bs[(f4k * 4 + 1) * 128 + rowA] = bv0.y;
        Bs[(f4k * 4 + 2) * 128 + rowA] = bv0.z;
        Bs[(f4k * 4 + 3) * 128 + rowA] = bv0.w;
        Bs[(f4k * 4 + 0) * 128 + rowA + 64] = bv1.x;
        Bs[(f4k * 4 + 1) * 128 + rowA + 64] = bv1.y;
        Bs[(f4k * 4 + 2) * 128 + rowA + 64] = bv1.z;
        Bs[(f4k * 4 + 3) * 128 + rowA + 64] = bv1.w;
        __syncthreads();

        if (kb + 16 < EDIM) {
            av0 = *reinterpret_cast<const float4*>(emb + (size_t)idx0 * EDIM + kb + 16 + f4k * 4);
            av1 = *reinterpret_cast<const float4*>(emb + (size_t)idx1 * EDIM + kb + 16 + f4k * 4);
            bv0 = *reinterpret_cast<const float4*>(W + (size_t)nlb0 * EDIM + kb + 16 + f4k * 4);
            bv1 = *reinterpret_cast<const float4*>(W + (size_t)nlb1 * EDIM + kb + 16 + f4k * 4);
        }

#pragma unroll
        for (int k = 0; k < 16; k++) {
            const float* ap = As + k * 132 + ty * 8;
            ulonglong2 A01 = *reinterpret_cast<const ulonglong2*>(ap);
            ulonglong2 A23 = *reinterpret_cast<const ulonglong2*>(ap + 4);
            const float* bp = Bs + k * 128 + tx * 8;
            float4 b0 = *reinterpret_cast<const float4*>(bp);
            float4 b1 = *reinterpret_cast<const float4*>(bp + 4);
            u64 am[4] = {A01.x, A01.y, A23.x, A23.y};
            u64 bn[8];
            bn[0] = pack2(b0.x, b0.x); bn[1] = pack2(b0.y, b0.y);
            bn[2] = pack2(b0.z, b0.z); bn[3] = pack2(b0.w, b0.w);
            bn[4] = pack2(b1.x, b1.x); bn[5] = pack2(b1.y, b1.y);
            bn[6] = pack2(b1.z, b1.z); bn[7] = pack2(b1.w, b1.w);
#pragma unroll
            for (int i = 0; i < 4; i++)
#pragma unroll
                for (int j = 0; j < 8; j++) fma2(acc[i][j], am[i], bn[j]);
        }
        __syncthreads();
    }

    const int n0  = ntile * 128 + tx * 8;
    const int nl0 = n0 & 1023;
    const float* __restrict__ bih = dir ? bihb : bihf;
    const float* __restrict__ bhh = dir ? bhhb : bhhf;
    float bias[8];
#pragma unroll
    for (int j = 0; j < 8; j++) bias[j] = bih[nl0 + j] + bhh[nl0 + j];

#pragma unroll
    for (int i2 = 0; i2 < 4; i2++) {
        float2 v[8];
#pragma unroll
        for (int j = 0; j < 8; j++) v[j] = unpk(acc[i2][j]);
        const int m0 = mtile * 128 + ty * 8 + 2 * i2;
        float4 oa0, oa1, ob0, ob1;
        oa0.x = v[0].x + bias[0]; oa0.y = v[1].x + bias[1]; oa0.z = v[2].x + bias[2]; oa0.w = v[3].x + bias[3];
        oa1.x = v[4].x + bias[4]; oa1.y = v[5].x + bias[5]; oa1.z = v[6].x + bias[6]; oa1.w = v[7].x + bias[7];
        ob0.x = v[0].y + bias[0]; ob0.y = v[1].y + bias[1]; ob0.z = v[2].y + bias[2]; ob0.w = v[3].y + bias[3];
        ob1.x = v[4].y + bias[4]; ob1.y = v[5].y + bias[5]; ob1.z = v[6].y + bias[6]; ob1.w = v[7].y + bias[7];
        float* p0 = g_xg + ((size_t)dir * NTOK + m0) * G4H + nl0;
        float* p1 = g_xg + ((size_t)dir * NTOK + m0 + 1) * G4H + nl0;
        *reinterpret_cast<float4*>(p0)     = oa0;
        *reinterpret_cast<float4*>(p0 + 4) = oa1;
        *reinterpret_cast<float4*>(p1)     = ob0;
        *reinterpret_cast<float4*>(p1 + 4) = ob1;
    }
}

// ============================================================================
// Kernel 2: persistent BiLSTM. 128 CTAs = dir(2) x bg(8) x ug(8).  [R9 core]
//   Changes vs R9: (1) release = red.add.release.gpu (no MEMBAR);
//   (2) min-semantics staggered poll (8 warps' lane0 + smem early-exit flag);
//   (3) pre[] layout kc-contiguous (PRE_LD=76): gate reads 8 LDS.128 instead
//       of 32 scalar LDS; both STS and LDS.128 patterns bank-conflict-free.
// ============================================================================
#define HLD    260
#define PRE_LD 76

__global__ __launch_bounds__(256, 1) void lstm_kernel(
    const float* __restrict__ whhf, const float* __restrict__ whhb)
{
    __shared__ float hs[8 * HLD];        // staged h_prev [batch][256]
    __shared__ float pre[128 * PRE_LD];  // [row][b*8 + kc]
    __shared__ int   smflag;             // last step whose wait completed

    const int tid = threadIdx.x;
    const int blk = blockIdx.x;
    const int dir = blk >> 6;
    const int bg  = (blk >> 3) & 7;
    const int ug  = blk & 7;
    const float* __restrict__ whh = dir ? whhb : whhf;

    if (tid == 0) smflag = 0;

    const int kc = tid & 7;           // k slice
    const int r4 = tid >> 3;          // local unit 0..31 -> rows G*256 + ug*32 + r4

    // register weights: 4 gate rows x 32 k (16 pairs) each
    u64 w[4][16];
#pragma unroll
    for (int G = 0; G < 4; G++) {
        const float* wr = whh + (size_t)(G * 256 + ug * 32 + r4) * HDIM2;
#pragma unroll
        for (int q = 0; q < 8; q++) {
            ulonglong2 v = *reinterpret_cast<const ulonglong2*>(wr + q * 32 + kc * 4);
            w[G][2 * q] = v.x; w[G][2 * q + 1] = v.y;
        }
    }

    const int gb = tid >> 5;          // gate phase: batch 0..7
    const int gu = tid & 31;          // unit-in-slice 0..31
    const int b_glob = bg * 8 + gb;
    const int unit = ug * 32 + gu;
    const int cnt_idx = dir * 8 + bg;
    int* cnt = &g_cnt[cnt_idx];
    float c_state = 0.f;
    __syncthreads();   // smflag init visible

    for (int t = 0; t < SEQ; t++) {
        const int pos = dir ? (SEQ - 1 - t) : t;

        // prefetch x-preacts before the inter-CTA wait
        const float* xp = g_xg + ((size_t)dir * NTOK + (size_t)b_glob * SEQ + pos) * G4H + unit;
        float x0 = __ldcs(xp);
        float x1 = __ldcs(xp + 256);
        float x2 = __ldcs(xp + 512);
        float x3 = __ldcs(xp + 768);

        if (t > 0) {
            // min-semantics poll: lane0 of each warp polls; first discoverer
            // publishes via smem flag; ordering carried by the bar below.
            if ((tid & 31) == 0) {
                volatile int* sf = &smflag;
                const int target = 8 * t;
                while (*sf < t) {
                    if (ld_acq_gpu(cnt) >= target) { *sf = t; break; }
                }
            }
            __syncthreads();
            const int ppos = dir ? (pos + 1) : (pos - 1);
            // stage h_prev for our 8 batches (512 float4 / 256 threads = 2 each)
#pragma unroll
            for (int q = 0; q < 2; q++) {
                const int id = tid + q * 256;
                const int b = id >> 6, kf4 = id & 63;
                float4 v = __ldcg(reinterpret_cast<const float4*>(
                    g_h + ((size_t)(dir * BATCH + bg * 8 + b) * SEQ + ppos) * HDIM2 + kf4 * 4));
                *reinterpret_cast<float4*>(hs + b * HLD + kf4 * 4) = v;
            }
            __syncthreads();

            // matvec: 4 gate rows x 8 batches x 32 k, in 2 passes of 4 batches
#pragma unroll
            for (int p = 0; p < 2; p++) {
                u64 acc[4][4];
#pragma unroll
                for (int G = 0; G < 4; G++)
#pragma unroll
                    for (int b = 0; b < 4; b++) acc[G][b] = 0ull;
#pragma unroll
                for (int q = 0; q < 8; q++) {
#pragma unroll
                    for (int b = 0; b < 4; b++) {
                        const ulonglong2 hv = *reinterpret_cast<const ulonglong2*>(
                            hs + (p * 4 + b) * HLD + q * 32 + kc * 4);
#pragma unroll
                        for (int G = 0; G < 4; G++) {
                            fma2(acc[G][b], w[G][2 * q],     hv.x);
                            fma2(acc[G][b], w[G][2 * q + 1], hv.y);
                        }
                    }
                }
#pragma unroll
                for (int G = 0; G < 4; G++)
#pragma unroll
                    for (int b = 0; b < 4; b++)
                        pre[(G * 32 + r4) * PRE_LD + (p * 4 + b) * 8 + kc] = foldlohi(acc[G][b]);
            }
            __syncthreads();
        }

        // gate phase: thread owns (batch gb, unit gu); 2x LDS.128 per gate
        {
            float pi = x0, pf = x1, pg = x2, po = x3;
            if (t > 0) {
                float s[4];
#pragma unroll
                for (int G = 0; G < 4; G++) {
                    const float* pp = pre + (G * 32 + gu) * PRE_LD + gb * 8;
                    float4 a = *reinterpret_cast<const float4*>(pp);
                    float4 b = *reinterpret_cast<const float4*>(pp + 4);
                    s[G] = ((a.x + a.y) + (a.z + a.w)) + ((b.x + b.y) + (b.z + b.w));
                }
                pi += s[0]; pf += s[1]; pg += s[2]; po += s[3];
            }
            c_state = sigf(pf) * c_state + sigf(pi) * tanhfast(pg);
            const float hv = sigf(po) * tanhfast(c_state);
            __stcg(&g_h[((size_t)(dir * BATCH + b_glob) * SEQ + pos) * HDIM2 + unit], hv);
        }

        __syncthreads();   // all h stores program-ordered before the release
        if (tid == 0) red_add_release_gpu(cnt);
    }
}

// ============================================================================
// Kernel 3: output projection
// ============================================================================
__global__ __launch_bounds__(256) void feats_kernel(
    const float* __restrict__ wout, const float* __restrict__ bout)
{
    __shared__ float wsm[NTAGS * 512];
    const int tid = threadIdx.x;
    for (int i = tid; i < NTAGS * 512; i += 256) wsm[i] = wout[i];
    __syncthreads();

    const int lane = tid & 31;
    const int warp = tid >> 5;

#pragma unroll
    for (int pass = 0; pass < 4; pass++) {
        const int m = blockIdx.x * 32 + pass * 8 + warp;
        const float* h0 = g_h + (size_t)m * HDIM2;
        const float* h1 = g_h + (size_t)NTOK * HDIM2 + (size_t)m * HDIM2;
        float acc[NTAGS];
#pragma unroll
        for (int tg = 0; tg < NTAGS; tg++) acc[tg] = 0.f;

#pragma unroll
        for (int kk = 0; kk < 16; kk++) {
            const int k = kk * 32 + lane;
            const float hv = (k < 256) ? h0[k] : h1[k - 256];
#pragma unroll
            for (int tg = 0; tg < NTAGS; tg++) acc[tg] += hv * wsm[tg * 512 + k];
        }
#pragma unroll
        for (int tg = 0; tg < NTAGS; tg++)
            for (int off = 16; off; off >>= 1)
                acc[tg] += __shfl_down_sync(0xffffffffu, acc[tg], off);
        if (lane == 0) {
#pragma unroll
            for (int tg = 0; tg < NTAGS; tg++)
                g_feats[(size_t)m * NTAGS + tg] = acc[tg] + bout[tg];
        }
    }
}

// ============================================================================
// Kernel 4: CRF per-sequence llh (mask all-ones)
// ============================================================================
__global__ __launch_bounds__(32) void crf_kernel(
    const int* __restrict__ tags,
    const float* __restrict__ startt, const float* __restrict__ endt,
    const float* __restrict__ trans)
{
    const int b = blockIdx.x;
    const int lane = threadIdx.x;
    const float* __restrict__ em = g_feats + (size_t)b * SEQ * NTAGS;
    const int* __restrict__ tg = tags + (size_t)b * SEQ;

    float sc = 0.f;
    for (int s = lane; s < SEQ; s += 32) {
        const int tc = tg[s];
        sc += em[s * NTAGS + tc];
        if (s > 0) sc += trans[tg[s - 1] * NTAGS + tc];
    }
    for (int off = 16; off; off >>= 1) sc += __shfl_down_sync(0xffffffffu, sc, off);

    const int j = lane < NTAGS ? lane : NTAGS - 1;
    float tcol[NTAGS];
#pragma unroll
    for (int i = 0; i < NTAGS; i++) tcol[i] = trans[i * NTAGS + j];

    float alpha = startt[j] + em[j];
    for (int s = 1; s < SEQ; s++) {
        float v[NTAGS];
        float mx = -1e30f;
#pragma unroll
        for (int i = 0; i < NTAGS; i++) {
            const float ai = __shfl_sync(0xffffffffu, alpha, i);
            v[i] = ai + tcol[i];
            mx = fmaxf(mx, v[i]);
        }
        float sum = 0.f;
#pragma unroll
        for (int i = 0; i < NTAGS; i++) sum += __expf(v[i] - mx);
        alpha = mx + __logf(sum) + em[s * NTAGS + j];
    }

    float z = (lane < NTAGS) ? (alpha + endt[j]) : -1e30f;
    float mz = z;
    for (int off = 16; off; off >>= 1) mz = fmaxf(mz, __shfl_down_sync(0xffffffffu, mz, off));
    mz = __shfl_sync(0xffffffffu, mz, 0);
    float ez = __expf(z - mz);
    for (int off = 16; off; off >>= 1) ez += __shfl_down_sync(0xffffffffu, ez, off);

    if (lane == 0) {
        const float logZ = mz + __logf(ez);
        const float score = sc + startt[tg[0]] + endt[tg[SEQ - 1]];
        g_llh[b] = score - logZ;
    }
}

__global__ void final_kernel(float* out) {
    __shared__ float red[64];
    const int t = threadIdx.x;
    red[t] = g_llh[t];
    __syncthreads();
    for (int off = 32; off; off >>= 1) {
        if (t < off) red[t] += red[t + off];
        __syncthreads();
    }
    if (t == 0) out[0] = -red[0] / (float)BATCH;
}

// ============================================================================
extern "C" void kernel_launch(void* const* d_in, const int* in_sizes, int n_in,
                              void* d_out, int out_size)
{
    const int*   sent  = (const int*)  d_in[0];
    const int*   tags  = (const int*)  d_in[1];
    const float* emb   = (const float*)d_in[3];
    const float* wihf  = (const float*)d_in[4];
    const float* whhf  = (const float*)d_in[5];
    const float* bihf  = (const float*)d_in[6];
    const float* bhhf  = (const float*)d_in[7];
    const float* wihb  = (const float*)d_in[8];
    const float* whhb  = (const float*)d_in[9];
    const float* bihb  = (const float*)d_in[10];
    const float* bhhb  = (const float*)d_in[11];
    const float* wout  = (const float*)d_in[12];
    const float* bout  = (const float*)d_in[13];
    const float* startt= (const float*)d_in[14];
    const float* endt  = (const float*)d_in[15];
    const float* trans = (const float*)d_in[16];

    gemm_xg_kernel<<<dim3(16, 256), 256>>>(sent, emb, wihf, wihb, bihf, bhhf, bihb, bhhb);
    lstm_kernel<<<128, 256>>>(whhf, whhb);
    feats_kernel<<<1024, 256>>>(wout, bout);
    crf_kernel<<<64, 32>>>(tags, startt, endt, trans);
    final_kernel<<<1, 64>>>((float*)d_out);
}